// round 14
// baseline (speedup 1.0000x reference)
#include <cuda_runtime.h>
#include <cuda_fp16.h>
#include <math.h>
#include <stdint.h>

#define N_NODES 50000
#define N_EDGES 800000
#define EE (N_EDGES + N_NODES)   /* 850000 edges incl. self loops */
#define DIN 128
#define F1 128
#define F2 64
#define PAD 80                   /* padded CSR row stride; max deg << 80 */
#define FULLMASK 0xffffffffu
#define LOG2E 1.4426950408889634f

/* ------------------------ scratch (device globals) ------------------------ */
__device__ __half g_xl1[(size_t)N_NODES * F1];
__device__ __half g_xr1[(size_t)N_NODES * F1];
__device__ __half g_h[(size_t)N_NODES * F1];
__device__ __half g_xl2[(size_t)N_NODES * F2];
__device__ __half g_xr2[(size_t)N_NODES * F2];

__device__ int g_cnt[N_NODES];    /* zero at load; re-zeroed by node_l2 epilogue */
__device__ int g_src_pad[(size_t)N_NODES * PAD];

/* ------------------------------ helpers ---------------------------------- */
__device__ __forceinline__ float ex2(float x) {   /* raw MUFU.EX2 */
    float r;
    asm("ex2.approx.f32 %0, %1;" : "=f"(r) : "f"(x));
    return r;
}
__device__ __forceinline__ float lg2(float x) {   /* raw MUFU.LG2 */
    float r;
    asm("lg2.approx.f32 %0, %1;" : "=f"(r) : "f"(x));
    return r;
}

__device__ __forceinline__ void mma_f16(float& c0, float& c1, float& c2, float& c3,
                                        uint32_t a0, uint32_t a1, uint32_t a2, uint32_t a3,
                                        uint32_t b0, uint32_t b1) {
    asm volatile("mma.sync.aligned.m16n8k16.row.col.f32.f16.f16.f32 "
                 "{%0,%1,%2,%3},{%4,%5,%6,%7},{%8,%9},{%0,%1,%2,%3};"
                 : "+f"(c0), "+f"(c1), "+f"(c2), "+f"(c3)
                 : "r"(a0), "r"(a1), "r"(a2), "r"(a3), "r"(b0), "r"(b1));
}

__device__ __forceinline__ uint32_t cvta_smem(const void* p) {
    uint32_t a;
    asm("{ .reg .u64 t; cvta.to.shared.u64 t, %1; cvt.u32.u64 %0, t; }"
        : "=r"(a) : "l"(p));
    return a;
}

__device__ __forceinline__ void ldsm_x4(uint32_t& r0, uint32_t& r1,
                                        uint32_t& r2, uint32_t& r3, uint32_t addr) {
    asm volatile("ldmatrix.sync.aligned.m8n8.x4.shared.b16 {%0,%1,%2,%3}, [%4];"
                 : "=r"(r0), "=r"(r1), "=r"(r2), "=r"(r3) : "r"(addr));
}

__device__ __forceinline__ void h4_to_f4(uint2 u, float& f0, float& f1, float& f2, float& f3) {
    __half2 p0 = *(__half2*)&u.x;
    __half2 p1 = *(__half2*)&u.y;
    float2 a = __half22float2(p0);
    float2 b = __half22float2(p1);
    f0 = a.x; f1 = a.y; f2 = b.x; f3 = b.y;
}

/* half2 leaky-relu: lrelu(t) = max(t, 0.2*t) */
__device__ __forceinline__ __half2 lrelu2(__half2 t) {
    const __half2 c = __floats2half2_rn(0.2f, 0.2f);
    return __hmax2(t, __hmul2(t, c));
}

/* fast ELU: v>0 ? v : e^v - 1  (MUFU-based) */
__device__ __forceinline__ float elu_fast(float v) {
    return v > 0.f ? v : (ex2(v * LOG2E) - 1.f);
}

/* packed fp32x2 helpers (FFMA2) */
__device__ __forceinline__ unsigned long long pack2(float x, float y) {
    unsigned long long r;
    asm("mov.b64 %0, {%1, %2};" : "=l"(r) : "f"(x), "f"(y));
    return r;
}
__device__ __forceinline__ void unpack2(unsigned long long p, float& x, float& y) {
    asm("mov.b64 {%0, %1}, %2;" : "=f"(x), "=f"(y) : "l"(p));
}
__device__ __forceinline__ void ffma2(unsigned long long& acc, unsigned long long a,
                                      unsigned long long b) {
    asm("fma.rn.f32x2 %0, %1, %2, %0;" : "+l"(acc) : "l"(a), "l"(b));
}

/* ------------------------- padded CSR scatter ----------------------------- */
__global__ void scatter_kernel(const int* __restrict__ ei) {
    int t = blockIdx.x * blockDim.x + threadIdx.x;
    int e0 = t * 8;
    if (e0 >= EE) return;
    if (e0 + 8 <= N_EDGES) {                  /* N_EDGES % 8 == 0 */
        int4 sa = *(const int4*)(ei + e0);
        int4 sb = *(const int4*)(ei + e0 + 4);
        int4 da = *(const int4*)(ei + N_EDGES + e0);
        int4 db = *(const int4*)(ei + N_EDGES + e0 + 4);
        int p;
        p = atomicAdd(&g_cnt[da.x], 1); if (p < PAD) g_src_pad[(size_t)da.x * PAD + p] = sa.x;
        p = atomicAdd(&g_cnt[da.y], 1); if (p < PAD) g_src_pad[(size_t)da.y * PAD + p] = sa.y;
        p = atomicAdd(&g_cnt[da.z], 1); if (p < PAD) g_src_pad[(size_t)da.z * PAD + p] = sa.z;
        p = atomicAdd(&g_cnt[da.w], 1); if (p < PAD) g_src_pad[(size_t)da.w * PAD + p] = sa.w;
        p = atomicAdd(&g_cnt[db.x], 1); if (p < PAD) g_src_pad[(size_t)db.x * PAD + p] = sb.x;
        p = atomicAdd(&g_cnt[db.y], 1); if (p < PAD) g_src_pad[(size_t)db.y * PAD + p] = sb.y;
        p = atomicAdd(&g_cnt[db.z], 1); if (p < PAD) g_src_pad[(size_t)db.z * PAD + p] = sb.z;
        p = atomicAdd(&g_cnt[db.w], 1); if (p < PAD) g_src_pad[(size_t)db.w * PAD + p] = sb.w;
    } else {
#pragma unroll
        for (int j = 0; j < 8; j++) {
            int e = e0 + j;
            if (e < EE) {
                int n = e - N_EDGES;          /* self loop region */
                int p = atomicAdd(&g_cnt[n], 1);
                if (p < PAD) g_src_pad[(size_t)n * PAD + p] = n;
            }
        }
    }
}

/* --------------------------- FP16 dual GEMM -------------------------------
 * M-tile 64, 128 threads (4 warps x 16 rows), up to 6 blocks/SM.
 * W chunk 0 load overlapped with X stage (independent smem buffers).
 */
template<int OUT, typename XT>
__global__ __launch_bounds__(128, 6)
void gemm_fp16(const XT* __restrict__ X,
               const float* __restrict__ Wl,
               const float* __restrict__ Wr,
               __half* __restrict__ outl,
               __half* __restrict__ outr) {
    constexpr int COLS2 = 2 * OUT;
    constexpr int NCH = COLS2 / 64;
    constexpr int LDK = 136;
    extern __shared__ __half smh[];
    __half* sX = smh;                 /* 64 x LDK */
    __half* sW = smh + 64 * LDK;      /* 64 x LDK (one chunk, transposed) */

    int tid = threadIdx.x;
    int warp = tid >> 5, lane = tid & 31;
    int g = lane >> 2, tig = lane & 3;
    int r0 = blockIdx.x * 64;
    int m0 = warp * 16;

    int lrow = lane & 7;
    int ltile = lane >> 3;
    uint32_t aBase = cvta_smem(&sX[(m0 + ((ltile & 1) << 3) + lrow) * LDK
                                   + ((ltile >> 1) << 3)]);
    uint32_t bBase = cvta_smem(&sW[(((lane >> 4) << 3) + lrow) * LDK
                                   + (((lane >> 3) & 1) << 3)]);

    /* X tile: 64 rows x 128 k -> fp16 smem (no sync needed vs W0 stage) */
    for (int idx = tid; idx < 64 * 32; idx += 128) {
        int r = idx >> 5, c4 = (idx & 31) << 2;
        float4 v = make_float4(0.f, 0.f, 0.f, 0.f);
        if (r0 + r < N_NODES) {
            if (sizeof(XT) == 2) {
                uint2 u = *(const uint2*)((const __half*)X + (size_t)(r0 + r) * DIN + c4);
                h4_to_f4(u, v.x, v.y, v.z, v.w);
            } else {
                v = *(const float4*)((const float*)X + (size_t)(r0 + r) * DIN + c4);
            }
        }
        __half2 p0 = __floats2half2_rn(v.x, v.y);
        __half2 p1 = __floats2half2_rn(v.z, v.w);
        uint2 pk;
        pk.x = *(uint32_t*)&p0;
        pk.y = *(uint32_t*)&p1;
        *(uint2*)&sX[r * LDK + c4] = pk;
    }
    /* W chunk 0: 64 cols x 128 k -> sW[n][k] (overlapped with X stage) */
    for (int idx = tid; idx < 64 * 64; idx += 128) {
        int k2 = idx >> 6, j = idx & 63;
        int k = k2 * 2;
        float w0 = Wl[(size_t)k * OUT + j];
        float w1 = Wl[(size_t)(k + 1) * OUT + j];
        *(__half2*)&sW[j * LDK + k] = __floats2half2_rn(w0, w1);
    }
    __syncthreads();

    for (int nc = 0; nc < NCH; nc++) {
        float acc[8][4];
#pragma unroll
        for (int nt = 0; nt < 8; nt++)
#pragma unroll
            for (int q = 0; q < 4; q++) acc[nt][q] = 0.f;

#pragma unroll
        for (int ks = 0; ks < 8; ks++) {
            int k0 = ks * 16;
            uint32_t a0, a1, a2, a3;
            ldsm_x4(a0, a1, a2, a3, aBase + k0 * 2);
#pragma unroll
            for (int j = 0; j < 4; j++) {
                uint32_t b0, b1, b2, b3;
                ldsm_x4(b0, b1, b2, b3, bBase + (j * 16 * LDK + k0) * 2);
                mma_f16(acc[2 * j][0], acc[2 * j][1], acc[2 * j][2], acc[2 * j][3],
                        a0, a1, a2, a3, b0, b1);
                mma_f16(acc[2 * j + 1][0], acc[2 * j + 1][1],
                        acc[2 * j + 1][2], acc[2 * j + 1][3],
                        a0, a1, a2, a3, b2, b3);
            }
        }

#pragma unroll
        for (int nt = 0; nt < 8; nt++) {
            int col = nc * 64 + nt * 8 + 2 * tig;
            __half* o = (col < OUT) ? outl : outr;
            int oc = (col < OUT) ? col : col - OUT;
            int row0 = r0 + m0 + g;
            if (row0 < N_NODES)
                *(__half2*)(o + (size_t)row0 * OUT + oc) = __floats2half2_rn(acc[nt][0], acc[nt][1]);
            int row1 = row0 + 8;
            if (row1 < N_NODES)
                *(__half2*)(o + (size_t)row1 * OUT + oc) = __floats2half2_rn(acc[nt][2], acc[nt][3]);
        }

        if (nc + 1 < NCH) {
            __syncthreads();   /* all sW reads done */
            const float* Wsrc = ((nc + 1) * 64 < OUT) ? Wl : Wr;
            int cbase = ((nc + 1) * 64) % OUT;
            for (int idx = tid; idx < 64 * 64; idx += 128) {
                int k2 = idx >> 6, j = idx & 63;
                int k = k2 * 2;
                float w0 = Wsrc[(size_t)k * OUT + cbase + j];
                float w1 = Wsrc[(size_t)(k + 1) * OUT + cbase + j];
                *(__half2*)&sW[j * LDK + k] = __floats2half2_rn(w0, w1);
            }
            __syncthreads();
        }
    }
}

/* -------------------- layer 1: fused softmax aggregation ------------------
 * 16 lanes per node (2 nodes/warp), 8 channels/lane, LDG.128 gathers.
 * Epilogue applies b1 + ELU so gemm2 reads h pre-activated.
 */
__global__ void node_l1_kernel(const float* __restrict__ att1,
                               const float* __restrict__ b1) {
    int gt = blockIdx.x * blockDim.x + threadIdx.x;
    int n = gt >> 4, l = gt & 15;
    if (n >= N_NODES) return;
    int lane = threadIdx.x & 31;
    const unsigned gmask = (lane < 16) ? 0x0000ffffu : 0xffff0000u;
    int cnt = g_cnt[n]; if (cnt > PAD) cnt = PAD;
    const int* srow = g_src_pad + (size_t)n * PAD;

    uint4 xr = *(const uint4*)(g_xr1 + (size_t)n * F1 + l * 8);
    __half2 xrh[4] = { *(__half2*)&xr.x, *(__half2*)&xr.y,
                       *(__half2*)&xr.z, *(__half2*)&xr.w };
    float4 wa = *(const float4*)(att1 + l * 8);
    float4 wb = *(const float4*)(att1 + l * 8 + 4);
    __half2 wh[4] = { __floats2half2_rn(wa.x * LOG2E, wa.y * LOG2E),
                      __floats2half2_rn(wa.z * LOG2E, wa.w * LOG2E),
                      __floats2half2_rn(wb.x * LOG2E, wb.y * LOG2E),
                      __floats2half2_rn(wb.z * LOG2E, wb.w * LOG2E) };
    unsigned long long ac[4] = { pack2(0.f, 0.f), pack2(0.f, 0.f),
                                 pack2(0.f, 0.f), pack2(0.f, 0.f) };
    float den = 0.f;

    int s0 = srow[0];
    uint4 A0 = *(const uint4*)(g_xl1 + (size_t)s0 * F1 + l * 8);
    uint4 A1 = A0;
    if (cnt > 1) {
        int s1 = srow[1];
        A1 = *(const uint4*)(g_xl1 + (size_t)s1 * F1 + l * 8);
    }
    for (int i = 0; i < cnt; i++) {
        uint4 cur = A0;
        A0 = A1;
        if (i + 2 < cnt) {
            int s2 = srow[i + 2];
            A1 = *(const uint4*)(g_xl1 + (size_t)s2 * F1 + l * 8);
        }
        __half2 h0 = *(__half2*)&cur.x;
        __half2 h1 = *(__half2*)&cur.y;
        __half2 h2 = *(__half2*)&cur.z;
        __half2 h3 = *(__half2*)&cur.w;
        __half2 t01 = __hfma2(lrelu2(__hadd2(h0, xrh[0])), wh[0],
                              __hmul2(lrelu2(__hadd2(h1, xrh[1])), wh[1]));
        __half2 t23 = __hfma2(lrelu2(__hadd2(h2, xrh[2])), wh[2],
                              __hmul2(lrelu2(__hadd2(h3, xrh[3])), wh[3]));
        float2 tf = __half22float2(__hadd2(t01, t23));
        float v = tf.x + tf.y;
        v += __shfl_xor_sync(gmask, v, 1, 16);   /* head = lane pair */
        float ex = ex2(v);
        den += ex;
        unsigned long long exx = pack2(ex, ex);
        float2 a0 = __half22float2(h0), a1 = __half22float2(h1);
        float2 a2 = __half22float2(h2), a3 = __half22float2(h3);
        ffma2(ac[0], pack2(a0.x, a0.y), exx);
        ffma2(ac[1], pack2(a1.x, a1.y), exx);
        ffma2(ac[2], pack2(a2.x, a2.y), exx);
        ffma2(ac[3], pack2(a3.x, a3.y), exx);
    }
    float inv = 1.0f / den;
    float4 bb0 = *(const float4*)(b1 + l * 8);
    float4 bb1 = *(const float4*)(b1 + l * 8 + 4);
    float x0, x1, x2, x3, x4, x5, x6, x7;
    unpack2(ac[0], x0, x1); unpack2(ac[1], x2, x3);
    unpack2(ac[2], x4, x5); unpack2(ac[3], x6, x7);
    x0 = elu_fast(fmaf(x0, inv, bb0.x));
    x1 = elu_fast(fmaf(x1, inv, bb0.y));
    x2 = elu_fast(fmaf(x2, inv, bb0.z));
    x3 = elu_fast(fmaf(x3, inv, bb0.w));
    x4 = elu_fast(fmaf(x4, inv, bb1.x));
    x5 = elu_fast(fmaf(x5, inv, bb1.y));
    x6 = elu_fast(fmaf(x6, inv, bb1.z));
    x7 = elu_fast(fmaf(x7, inv, bb1.w));
    __half2 q0 = __floats2half2_rn(x0, x1);
    __half2 q1 = __floats2half2_rn(x2, x3);
    __half2 q2 = __floats2half2_rn(x4, x5);
    __half2 q3 = __floats2half2_rn(x6, x7);
    uint4 pk;
    pk.x = *(uint32_t*)&q0; pk.y = *(uint32_t*)&q1;
    pk.z = *(uint32_t*)&q2; pk.w = *(uint32_t*)&q3;
    *(uint4*)(g_h + (size_t)n * F1 + l * 8) = pk;
}

/* ---- layer 2: fused softmax agg + bias + log_softmax (8 lanes/node) ------ */
__global__ void node_l2_kernel(const float* __restrict__ att2,
                               const float* __restrict__ b2,
                               float* __restrict__ out) {
    int gt = blockIdx.x * blockDim.x + threadIdx.x;
    int n = gt >> 3, l = gt & 7;
    if (n >= N_NODES) return;
    int lane = threadIdx.x & 31;
    const unsigned gmask = 0xffu << ((lane >> 3) << 3);
    int cnt = g_cnt[n]; if (cnt > PAD) cnt = PAD;
    const int* srow = g_src_pad + (size_t)n * PAD;

    uint4 xr = *(const uint4*)(g_xr2 + (size_t)n * F2 + l * 8);
    __half2 xrh[4] = { *(__half2*)&xr.x, *(__half2*)&xr.y,
                       *(__half2*)&xr.z, *(__half2*)&xr.w };
    float4 wa = *(const float4*)(att2 + l * 8);
    float4 wb = *(const float4*)(att2 + l * 8 + 4);
    __half2 wh[4] = { __floats2half2_rn(wa.x * LOG2E, wa.y * LOG2E),
                      __floats2half2_rn(wa.z * LOG2E, wa.w * LOG2E),
                      __floats2half2_rn(wb.x * LOG2E, wb.y * LOG2E),
                      __floats2half2_rn(wb.z * LOG2E, wb.w * LOG2E) };
    unsigned long long ac[4] = { pack2(0.f, 0.f), pack2(0.f, 0.f),
                                 pack2(0.f, 0.f), pack2(0.f, 0.f) };
    float den = 0.f;

    int s0 = srow[0];
    uint4 A0 = *(const uint4*)(g_xl2 + (size_t)s0 * F2 + l * 8);
    uint4 A1 = A0;
    if (cnt > 1) {
        int s1 = srow[1];
        A1 = *(const uint4*)(g_xl2 + (size_t)s1 * F2 + l * 8);
    }
    for (int i = 0; i < cnt; i++) {
        uint4 cur = A0;
        A0 = A1;
        if (i + 2 < cnt) {
            int s2 = srow[i + 2];
            A1 = *(const uint4*)(g_xl2 + (size_t)s2 * F2 + l * 8);
        }
        __half2 h0 = *(__half2*)&cur.x;
        __half2 h1 = *(__half2*)&cur.y;
        __half2 h2 = *(__half2*)&cur.z;
        __half2 h3 = *(__half2*)&cur.w;
        __half2 t01 = __hfma2(lrelu2(__hadd2(h0, xrh[0])), wh[0],
                              __hmul2(lrelu2(__hadd2(h1, xrh[1])), wh[1]));
        __half2 t23 = __hfma2(lrelu2(__hadd2(h2, xrh[2])), wh[2],
                              __hmul2(lrelu2(__hadd2(h3, xrh[3])), wh[3]));
        float2 tf = __half22float2(__hadd2(t01, t23));
        float v = tf.x + tf.y;
        v += __shfl_xor_sync(gmask, v, 1, 8);
        v += __shfl_xor_sync(gmask, v, 2, 8);
        v += __shfl_xor_sync(gmask, v, 4, 8);
        float ex = ex2(v);
        den += ex;
        unsigned long long exx = pack2(ex, ex);
        float2 a0 = __half22float2(h0), a1 = __half22float2(h1);
        float2 a2 = __half22float2(h2), a3 = __half22float2(h3);
        ffma2(ac[0], pack2(a0.x, a0.y), exx);
        ffma2(ac[1], pack2(a1.x, a1.y), exx);
        ffma2(ac[2], pack2(a2.x, a2.y), exx);
        ffma2(ac[3], pack2(a3.x, a3.y), exx);
    }
    float inv = 1.0f / den;
    float o[8];
    unpack2(ac[0], o[0], o[1]); unpack2(ac[1], o[2], o[3]);
    unpack2(ac[2], o[4], o[5]); unpack2(ac[3], o[6], o[7]);
    float4 bb0 = *(const float4*)(b2 + l * 8);
    float4 bb1 = *(const float4*)(b2 + l * 8 + 4);
    o[0] = fmaf(o[0], inv, bb0.x); o[1] = fmaf(o[1], inv, bb0.y);
    o[2] = fmaf(o[2], inv, bb0.z); o[3] = fmaf(o[3], inv, bb0.w);
    o[4] = fmaf(o[4], inv, bb1.x); o[5] = fmaf(o[5], inv, bb1.y);
    o[6] = fmaf(o[6], inv, bb1.z); o[7] = fmaf(o[7], inv, bb1.w);

    float mx = o[0];
#pragma unroll
    for (int c = 1; c < 8; c++) mx = fmaxf(mx, o[c]);
#pragma unroll
    for (int q = 4; q; q >>= 1) mx = fmaxf(mx, __shfl_xor_sync(gmask, mx, q, 8));
    float sum = 0.f;
#pragma unroll
    for (int c = 0; c < 8; c++) sum += ex2((o[c] - mx) * LOG2E);
#pragma unroll
    for (int q = 4; q; q >>= 1) sum += __shfl_xor_sync(gmask, sum, q, 8);
    float lse = fmaf(lg2(sum), 1.0f / LOG2E, mx);
    float4 r0 = make_float4(o[0] - lse, o[1] - lse, o[2] - lse, o[3] - lse);
    float4 r1 = make_float4(o[4] - lse, o[5] - lse, o[6] - lse, o[7] - lse);
    *(float4*)(out + (size_t)n * F2 + l * 8)     = r0;
    *(float4*)(out + (size_t)n * F2 + l * 8 + 4) = r1;

    if (l == 0) g_cnt[n] = 0;    /* reset for next call */
}

/* ------------------------------ launch ------------------------------------ */
extern "C" void kernel_launch(void* const* d_in, const int* in_sizes, int n_in,
                              void* d_out, int out_size) {
    const float* x    = (const float*)d_in[0];
    const int*   ei   = (const int*)d_in[1];
    const float* Wl1  = (const float*)d_in[2];
    const float* Wr1  = (const float*)d_in[3];
    const float* att1 = (const float*)d_in[4];
    const float* b1   = (const float*)d_in[5];
    const float* Wl2  = (const float*)d_in[6];
    const float* Wr2  = (const float*)d_in[7];
    const float* att2 = (const float*)d_in[8];
    const float* b2   = (const float*)d_in[9];
    float* out = (float*)d_out;

    __half *p_xl1, *p_xr1, *p_h, *p_xl2, *p_xr2;
    cudaGetSymbolAddress((void**)&p_xl1, g_xl1);
    cudaGetSymbolAddress((void**)&p_xr1, g_xr1);
    cudaGetSymbolAddress((void**)&p_h,   g_h);
    cudaGetSymbolAddress((void**)&p_xl2, g_xl2);
    cudaGetSymbolAddress((void**)&p_xr2, g_xr2);

    const int smem = (64 * 136 + 64 * 136) * (int)sizeof(__half);  /* 34816 */

    const int TB = 256;
    int e8_grid = (EE / 8 + TB) / TB;
    int gemm_grid = (N_NODES + 63) / 64;       /* 782 */

    /* fork: scatter on side stream, gemm1 on main (capturing) stream. */
    cudaStream_t s2;
    cudaStreamCreateWithFlags(&s2, cudaStreamNonBlocking);
    cudaEvent_t evA, evB;
    cudaEventCreateWithFlags(&evA, cudaEventDisableTiming);
    cudaEventCreateWithFlags(&evB, cudaEventDisableTiming);

    cudaEventRecord(evA, 0);
    cudaStreamWaitEvent(s2, evA, 0);
    scatter_kernel<<<e8_grid, TB, 0, s2>>>(ei);
    cudaEventRecord(evB, s2);

    gemm_fp16<128, float><<<gemm_grid, 128, smem>>>(x, Wl1, Wr1, p_xl1, p_xr1);

    cudaStreamWaitEvent(0, evB, 0);   /* join: node_l1 needs scatter + gemm1 */
    node_l1_kernel<<<(N_NODES * 16 + TB - 1) / TB, TB>>>(att1, b1);

    /* gemm2: h already bias+ELU'd by node_l1 epilogue */
    gemm_fp16<64, __half><<<gemm_grid, 128, smem>>>(p_h, Wl2, Wr2, p_xl2, p_xr2);
    node_l2_kernel<<<(N_NODES * 8 + TB - 1) / TB, TB>>>(att2, b2, out);
    /* s2/evA/evB intentionally not destroyed (graph-capture safety; no
       tracked device memory held). */
}

// round 15
// speedup vs baseline: 1.5552x; 1.5552x over previous
#include <cuda_runtime.h>
#include <cuda_fp16.h>
#include <math.h>
#include <stdint.h>

#define N_NODES 50000
#define N_EDGES 800000
#define EE (N_EDGES + N_NODES)   /* 850000 edges incl. self loops */
#define DIN 128
#define F1 128
#define F2 64
#define PAD 80                   /* padded CSR row stride; max deg << 80 */
#define FULLMASK 0xffffffffu
#define LOG2E 1.4426950408889634f

/* ------------------------ scratch (device globals) ------------------------ */
__device__ __half g_xl1[(size_t)N_NODES * F1];
__device__ __half g_xr1[(size_t)N_NODES * F1];
__device__ __half g_h[(size_t)N_NODES * F1];
__device__ __half g_xl2[(size_t)N_NODES * F2];
__device__ __half g_xr2[(size_t)N_NODES * F2];

__device__ int g_cnt[N_NODES];    /* zero at load; re-zeroed by node_l2 epilogue */
__device__ int g_src_pad[(size_t)N_NODES * PAD];

/* ------------------------------ helpers ---------------------------------- */
__device__ __forceinline__ float ex2(float x) {   /* raw MUFU.EX2 */
    float r;
    asm("ex2.approx.f32 %0, %1;" : "=f"(r) : "f"(x));
    return r;
}
__device__ __forceinline__ float lg2(float x) {   /* raw MUFU.LG2 */
    float r;
    asm("lg2.approx.f32 %0, %1;" : "=f"(r) : "f"(x));
    return r;
}

__device__ __forceinline__ void mma_f16(float& c0, float& c1, float& c2, float& c3,
                                        uint32_t a0, uint32_t a1, uint32_t a2, uint32_t a3,
                                        uint32_t b0, uint32_t b1) {
    asm volatile("mma.sync.aligned.m16n8k16.row.col.f32.f16.f16.f32 "
                 "{%0,%1,%2,%3},{%4,%5,%6,%7},{%8,%9},{%0,%1,%2,%3};"
                 : "+f"(c0), "+f"(c1), "+f"(c2), "+f"(c3)
                 : "r"(a0), "r"(a1), "r"(a2), "r"(a3), "r"(b0), "r"(b1));
}

__device__ __forceinline__ uint32_t cvta_smem(const void* p) {
    uint32_t a;
    asm("{ .reg .u64 t; cvta.to.shared.u64 t, %1; cvt.u32.u64 %0, t; }"
        : "=r"(a) : "l"(p));
    return a;
}

__device__ __forceinline__ void ldsm_x4(uint32_t& r0, uint32_t& r1,
                                        uint32_t& r2, uint32_t& r3, uint32_t addr) {
    asm volatile("ldmatrix.sync.aligned.m8n8.x4.shared.b16 {%0,%1,%2,%3}, [%4];"
                 : "=r"(r0), "=r"(r1), "=r"(r2), "=r"(r3) : "r"(addr));
}

__device__ __forceinline__ void h4_to_f4(uint2 u, float& f0, float& f1, float& f2, float& f3) {
    __half2 p0 = *(__half2*)&u.x;
    __half2 p1 = *(__half2*)&u.y;
    float2 a = __half22float2(p0);
    float2 b = __half22float2(p1);
    f0 = a.x; f1 = a.y; f2 = b.x; f3 = b.y;
}

/* half2 leaky-relu: lrelu(t) = max(t, 0.2*t) */
__device__ __forceinline__ __half2 lrelu2(__half2 t) {
    const __half2 c = __floats2half2_rn(0.2f, 0.2f);
    return __hmax2(t, __hmul2(t, c));
}

/* fast ELU: v>0 ? v : e^v - 1  (MUFU-based) */
__device__ __forceinline__ float elu_fast(float v) {
    return v > 0.f ? v : (ex2(v * LOG2E) - 1.f);
}

/* packed fp32x2 helpers (FFMA2) */
__device__ __forceinline__ unsigned long long pack2(float x, float y) {
    unsigned long long r;
    asm("mov.b64 %0, {%1, %2};" : "=l"(r) : "f"(x), "f"(y));
    return r;
}
__device__ __forceinline__ void unpack2(unsigned long long p, float& x, float& y) {
    asm("mov.b64 {%0, %1}, %2;" : "=f"(x), "=f"(y) : "l"(p));
}
__device__ __forceinline__ void ffma2(unsigned long long& acc, unsigned long long a,
                                      unsigned long long b) {
    asm("fma.rn.f32x2 %0, %1, %2, %0;" : "+l"(acc) : "l"(a), "l"(b));
}

/* ------------------------- padded CSR scatter ----------------------------- */
__global__ void scatter_kernel(const int* __restrict__ ei) {
    int t = blockIdx.x * blockDim.x + threadIdx.x;
    int e0 = t * 8;
    if (e0 >= EE) return;
    if (e0 + 8 <= N_EDGES) {                  /* N_EDGES % 8 == 0 */
        int4 sa = *(const int4*)(ei + e0);
        int4 sb = *(const int4*)(ei + e0 + 4);
        int4 da = *(const int4*)(ei + N_EDGES + e0);
        int4 db = *(const int4*)(ei + N_EDGES + e0 + 4);
        int p;
        p = atomicAdd(&g_cnt[da.x], 1); if (p < PAD) g_src_pad[(size_t)da.x * PAD + p] = sa.x;
        p = atomicAdd(&g_cnt[da.y], 1); if (p < PAD) g_src_pad[(size_t)da.y * PAD + p] = sa.y;
        p = atomicAdd(&g_cnt[da.z], 1); if (p < PAD) g_src_pad[(size_t)da.z * PAD + p] = sa.z;
        p = atomicAdd(&g_cnt[da.w], 1); if (p < PAD) g_src_pad[(size_t)da.w * PAD + p] = sa.w;
        p = atomicAdd(&g_cnt[db.x], 1); if (p < PAD) g_src_pad[(size_t)db.x * PAD + p] = sb.x;
        p = atomicAdd(&g_cnt[db.y], 1); if (p < PAD) g_src_pad[(size_t)db.y * PAD + p] = sb.y;
        p = atomicAdd(&g_cnt[db.z], 1); if (p < PAD) g_src_pad[(size_t)db.z * PAD + p] = sb.z;
        p = atomicAdd(&g_cnt[db.w], 1); if (p < PAD) g_src_pad[(size_t)db.w * PAD + p] = sb.w;
    } else {
#pragma unroll
        for (int j = 0; j < 8; j++) {
            int e = e0 + j;
            if (e < EE) {
                int n = e - N_EDGES;          /* self loop region */
                int p = atomicAdd(&g_cnt[n], 1);
                if (p < PAD) g_src_pad[(size_t)n * PAD + p] = n;
            }
        }
    }
}

/* --------------------------- FP16 dual GEMM (R13 + occ 3) ----------------- */
template<int OUT, bool DO_ELU, typename XT>
__global__ __launch_bounds__(256, 3)
void gemm_fp16(const XT* __restrict__ X,
               const float* __restrict__ Wl,
               const float* __restrict__ Wr,
               const float* __restrict__ bin,
               __half* __restrict__ outl,
               __half* __restrict__ outr) {
    constexpr int COLS2 = 2 * OUT;
    constexpr int NCH = COLS2 / 64;
    constexpr int LDK = 136;
    extern __shared__ __half smh[];
    __half* sX = smh;                 /* 128 x LDK */
    __half* sW = smh + 128 * LDK;     /* 64 x LDK (one chunk, transposed) */

    int tid = threadIdx.x;
    int warp = tid >> 5, lane = tid & 31;
    int g = lane >> 2, tig = lane & 3;
    int r0 = blockIdx.x * 128;
    int m0 = warp * 16;

    int lrow = lane & 7;
    int ltile = lane >> 3;
    uint32_t aBase = cvta_smem(&sX[(m0 + ((ltile & 1) << 3) + lrow) * LDK
                                   + ((ltile >> 1) << 3)]);
    uint32_t bBase = cvta_smem(&sW[(((lane >> 4) << 3) + lrow) * LDK
                                   + (((lane >> 3) & 1) << 3)]);

    for (int idx = tid; idx < 128 * 32; idx += 256) {
        int r = idx >> 5, c4 = (idx & 31) << 2;
        float4 v = make_float4(0.f, 0.f, 0.f, 0.f);
        if (r0 + r < N_NODES) {
            if (sizeof(XT) == 2) {
                uint2 u = *(const uint2*)((const __half*)X + (size_t)(r0 + r) * DIN + c4);
                h4_to_f4(u, v.x, v.y, v.z, v.w);
            } else {
                v = *(const float4*)((const float*)X + (size_t)(r0 + r) * DIN + c4);
            }
            if (DO_ELU) {
                float4 b = *(const float4*)(bin + c4);
                v.x = elu_fast(v.x + b.x);
                v.y = elu_fast(v.y + b.y);
                v.z = elu_fast(v.z + b.z);
                v.w = elu_fast(v.w + b.w);
            }
        }
        __half2 p0 = __floats2half2_rn(v.x, v.y);
        __half2 p1 = __floats2half2_rn(v.z, v.w);
        uint2 pk;
        pk.x = *(uint32_t*)&p0;
        pk.y = *(uint32_t*)&p1;
        *(uint2*)&sX[r * LDK + c4] = pk;
    }

    for (int nc = 0; nc < NCH; nc++) {
        __syncthreads();
        const float* Wsrc = (nc * 64 < OUT) ? Wl : Wr;
        int cbase = (nc * 64) % OUT;
        for (int idx = tid; idx < 64 * 64; idx += 256) {
            int k2 = idx >> 6, j = idx & 63;
            int k = k2 * 2;
            float w0 = Wsrc[(size_t)k * OUT + cbase + j];
            float w1 = Wsrc[(size_t)(k + 1) * OUT + cbase + j];
            *(__half2*)&sW[j * LDK + k] = __floats2half2_rn(w0, w1);
        }
        __syncthreads();

        float acc[8][4];
#pragma unroll
        for (int nt = 0; nt < 8; nt++)
#pragma unroll
            for (int q = 0; q < 4; q++) acc[nt][q] = 0.f;

#pragma unroll
        for (int ks = 0; ks < 8; ks++) {
            int k0 = ks * 16;
            uint32_t a0, a1, a2, a3;
            ldsm_x4(a0, a1, a2, a3, aBase + k0 * 2);
#pragma unroll
            for (int j = 0; j < 4; j++) {
                uint32_t b0, b1, b2, b3;
                ldsm_x4(b0, b1, b2, b3, bBase + (j * 16 * LDK + k0) * 2);
                mma_f16(acc[2 * j][0], acc[2 * j][1], acc[2 * j][2], acc[2 * j][3],
                        a0, a1, a2, a3, b0, b1);
                mma_f16(acc[2 * j + 1][0], acc[2 * j + 1][1],
                        acc[2 * j + 1][2], acc[2 * j + 1][3],
                        a0, a1, a2, a3, b2, b3);
            }
        }

#pragma unroll
        for (int nt = 0; nt < 8; nt++) {
            int col = nc * 64 + nt * 8 + 2 * tig;
            __half* o = (col < OUT) ? outl : outr;
            int oc = (col < OUT) ? col : col - OUT;
            int row0 = r0 + m0 + g;
            if (row0 < N_NODES)
                *(__half2*)(o + (size_t)row0 * OUT + oc) = __floats2half2_rn(acc[nt][0], acc[nt][1]);
            int row1 = row0 + 8;
            if (row1 < N_NODES)
                *(__half2*)(o + (size_t)row1 * OUT + oc) = __floats2half2_rn(acc[nt][2], acc[nt][3]);
        }
    }
}

/* -------------------- layer 1: fused softmax aggregation ------------------
 * 16 lanes per node (2 nodes/warp), 8 channels/lane, LDG.128 gathers.
 * Epilogue applies b1 + ELU so gemm2 reads h pre-activated.
 */
__global__ void node_l1_kernel(const float* __restrict__ att1,
                               const float* __restrict__ b1) {
    int gt = blockIdx.x * blockDim.x + threadIdx.x;
    int n = gt >> 4, l = gt & 15;
    if (n >= N_NODES) return;
    int lane = threadIdx.x & 31;
    const unsigned gmask = (lane < 16) ? 0x0000ffffu : 0xffff0000u;
    int cnt = g_cnt[n]; if (cnt > PAD) cnt = PAD;
    const int* srow = g_src_pad + (size_t)n * PAD;

    uint4 xr = *(const uint4*)(g_xr1 + (size_t)n * F1 + l * 8);
    __half2 xrh[4] = { *(__half2*)&xr.x, *(__half2*)&xr.y,
                       *(__half2*)&xr.z, *(__half2*)&xr.w };
    float4 wa = *(const float4*)(att1 + l * 8);
    float4 wb = *(const float4*)(att1 + l * 8 + 4);
    __half2 wh[4] = { __floats2half2_rn(wa.x * LOG2E, wa.y * LOG2E),
                      __floats2half2_rn(wa.z * LOG2E, wa.w * LOG2E),
                      __floats2half2_rn(wb.x * LOG2E, wb.y * LOG2E),
                      __floats2half2_rn(wb.z * LOG2E, wb.w * LOG2E) };
    unsigned long long ac[4] = { pack2(0.f, 0.f), pack2(0.f, 0.f),
                                 pack2(0.f, 0.f), pack2(0.f, 0.f) };
    float den = 0.f;

    int s0 = srow[0];
    uint4 A0 = *(const uint4*)(g_xl1 + (size_t)s0 * F1 + l * 8);
    uint4 A1 = A0;
    if (cnt > 1) {
        int s1 = srow[1];
        A1 = *(const uint4*)(g_xl1 + (size_t)s1 * F1 + l * 8);
    }
    for (int i = 0; i < cnt; i++) {
        uint4 cur = A0;
        A0 = A1;
        if (i + 2 < cnt) {
            int s2 = srow[i + 2];
            A1 = *(const uint4*)(g_xl1 + (size_t)s2 * F1 + l * 8);
        }
        __half2 h0 = *(__half2*)&cur.x;
        __half2 h1 = *(__half2*)&cur.y;
        __half2 h2 = *(__half2*)&cur.z;
        __half2 h3 = *(__half2*)&cur.w;
        __half2 t01 = __hfma2(lrelu2(__hadd2(h0, xrh[0])), wh[0],
                              __hmul2(lrelu2(__hadd2(h1, xrh[1])), wh[1]));
        __half2 t23 = __hfma2(lrelu2(__hadd2(h2, xrh[2])), wh[2],
                              __hmul2(lrelu2(__hadd2(h3, xrh[3])), wh[3]));
        float2 tf = __half22float2(__hadd2(t01, t23));
        float v = tf.x + tf.y;
        v += __shfl_xor_sync(gmask, v, 1, 16);   /* head = lane pair */
        float ex = ex2(v);
        den += ex;
        unsigned long long exx = pack2(ex, ex);
        float2 a0 = __half22float2(h0), a1 = __half22float2(h1);
        float2 a2 = __half22float2(h2), a3 = __half22float2(h3);
        ffma2(ac[0], pack2(a0.x, a0.y), exx);
        ffma2(ac[1], pack2(a1.x, a1.y), exx);
        ffma2(ac[2], pack2(a2.x, a2.y), exx);
        ffma2(ac[3], pack2(a3.x, a3.y), exx);
    }
    float inv = 1.0f / den;
    float4 bb0 = *(const float4*)(b1 + l * 8);
    float4 bb1 = *(const float4*)(b1 + l * 8 + 4);
    float x0, x1, x2, x3, x4, x5, x6, x7;
    unpack2(ac[0], x0, x1); unpack2(ac[1], x2, x3);
    unpack2(ac[2], x4, x5); unpack2(ac[3], x6, x7);
    x0 = elu_fast(fmaf(x0, inv, bb0.x));
    x1 = elu_fast(fmaf(x1, inv, bb0.y));
    x2 = elu_fast(fmaf(x2, inv, bb0.z));
    x3 = elu_fast(fmaf(x3, inv, bb0.w));
    x4 = elu_fast(fmaf(x4, inv, bb1.x));
    x5 = elu_fast(fmaf(x5, inv, bb1.y));
    x6 = elu_fast(fmaf(x6, inv, bb1.z));
    x7 = elu_fast(fmaf(x7, inv, bb1.w));
    __half2 q0 = __floats2half2_rn(x0, x1);
    __half2 q1 = __floats2half2_rn(x2, x3);
    __half2 q2 = __floats2half2_rn(x4, x5);
    __half2 q3 = __floats2half2_rn(x6, x7);
    uint4 pk;
    pk.x = *(uint32_t*)&q0; pk.y = *(uint32_t*)&q1;
    pk.z = *(uint32_t*)&q2; pk.w = *(uint32_t*)&q3;
    *(uint4*)(g_h + (size_t)n * F1 + l * 8) = pk;
}

/* ---- layer 2: fused softmax agg + bias + log_softmax (8 lanes/node) ------ */
__global__ void node_l2_kernel(const float* __restrict__ att2,
                               const float* __restrict__ b2,
                               float* __restrict__ out) {
    int gt = blockIdx.x * blockDim.x + threadIdx.x;
    int n = gt >> 3, l = gt & 7;
    if (n >= N_NODES) return;
    int lane = threadIdx.x & 31;
    const unsigned gmask = 0xffu << ((lane >> 3) << 3);
    int cnt = g_cnt[n]; if (cnt > PAD) cnt = PAD;
    const int* srow = g_src_pad + (size_t)n * PAD;

    uint4 xr = *(const uint4*)(g_xr2 + (size_t)n * F2 + l * 8);
    __half2 xrh[4] = { *(__half2*)&xr.x, *(__half2*)&xr.y,
                       *(__half2*)&xr.z, *(__half2*)&xr.w };
    float4 wa = *(const float4*)(att2 + l * 8);
    float4 wb = *(const float4*)(att2 + l * 8 + 4);
    __half2 wh[4] = { __floats2half2_rn(wa.x * LOG2E, wa.y * LOG2E),
                      __floats2half2_rn(wa.z * LOG2E, wa.w * LOG2E),
                      __floats2half2_rn(wb.x * LOG2E, wb.y * LOG2E),
                      __floats2half2_rn(wb.z * LOG2E, wb.w * LOG2E) };
    unsigned long long ac[4] = { pack2(0.f, 0.f), pack2(0.f, 0.f),
                                 pack2(0.f, 0.f), pack2(0.f, 0.f) };
    float den = 0.f;

    int s0 = srow[0];
    uint4 A0 = *(const uint4*)(g_xl2 + (size_t)s0 * F2 + l * 8);
    uint4 A1 = A0;
    if (cnt > 1) {
        int s1 = srow[1];
        A1 = *(const uint4*)(g_xl2 + (size_t)s1 * F2 + l * 8);
    }
    for (int i = 0; i < cnt; i++) {
        uint4 cur = A0;
        A0 = A1;
        if (i + 2 < cnt) {
            int s2 = srow[i + 2];
            A1 = *(const uint4*)(g_xl2 + (size_t)s2 * F2 + l * 8);
        }
        __half2 h0 = *(__half2*)&cur.x;
        __half2 h1 = *(__half2*)&cur.y;
        __half2 h2 = *(__half2*)&cur.z;
        __half2 h3 = *(__half2*)&cur.w;
        __half2 t01 = __hfma2(lrelu2(__hadd2(h0, xrh[0])), wh[0],
                              __hmul2(lrelu2(__hadd2(h1, xrh[1])), wh[1]));
        __half2 t23 = __hfma2(lrelu2(__hadd2(h2, xrh[2])), wh[2],
                              __hmul2(lrelu2(__hadd2(h3, xrh[3])), wh[3]));
        float2 tf = __half22float2(__hadd2(t01, t23));
        float v = tf.x + tf.y;
        v += __shfl_xor_sync(gmask, v, 1, 8);
        v += __shfl_xor_sync(gmask, v, 2, 8);
        v += __shfl_xor_sync(gmask, v, 4, 8);
        float ex = ex2(v);
        den += ex;
        unsigned long long exx = pack2(ex, ex);
        float2 a0 = __half22float2(h0), a1 = __half22float2(h1);
        float2 a2 = __half22float2(h2), a3 = __half22float2(h3);
        ffma2(ac[0], pack2(a0.x, a0.y), exx);
        ffma2(ac[1], pack2(a1.x, a1.y), exx);
        ffma2(ac[2], pack2(a2.x, a2.y), exx);
        ffma2(ac[3], pack2(a3.x, a3.y), exx);
    }
    float inv = 1.0f / den;
    float o[8];
    unpack2(ac[0], o[0], o[1]); unpack2(ac[1], o[2], o[3]);
    unpack2(ac[2], o[4], o[5]); unpack2(ac[3], o[6], o[7]);
    float4 bb0 = *(const float4*)(b2 + l * 8);
    float4 bb1 = *(const float4*)(b2 + l * 8 + 4);
    o[0] = fmaf(o[0], inv, bb0.x); o[1] = fmaf(o[1], inv, bb0.y);
    o[2] = fmaf(o[2], inv, bb0.z); o[3] = fmaf(o[3], inv, bb0.w);
    o[4] = fmaf(o[4], inv, bb1.x); o[5] = fmaf(o[5], inv, bb1.y);
    o[6] = fmaf(o[6], inv, bb1.z); o[7] = fmaf(o[7], inv, bb1.w);

    float mx = o[0];
#pragma unroll
    for (int c = 1; c < 8; c++) mx = fmaxf(mx, o[c]);
#pragma unroll
    for (int q = 4; q; q >>= 1) mx = fmaxf(mx, __shfl_xor_sync(gmask, mx, q, 8));
    float sum = 0.f;
#pragma unroll
    for (int c = 0; c < 8; c++) sum += ex2((o[c] - mx) * LOG2E);
#pragma unroll
    for (int q = 4; q; q >>= 1) sum += __shfl_xor_sync(gmask, sum, q, 8);
    float lse = fmaf(lg2(sum), 1.0f / LOG2E, mx);
    float4 r0 = make_float4(o[0] - lse, o[1] - lse, o[2] - lse, o[3] - lse);
    float4 r1 = make_float4(o[4] - lse, o[5] - lse, o[6] - lse, o[7] - lse);
    *(float4*)(out + (size_t)n * F2 + l * 8)     = r0;
    *(float4*)(out + (size_t)n * F2 + l * 8 + 4) = r1;

    if (l == 0) g_cnt[n] = 0;    /* reset for next call */
}

/* ------------------------------ launch ------------------------------------ */
extern "C" void kernel_launch(void* const* d_in, const int* in_sizes, int n_in,
                              void* d_out, int out_size) {
    const float* x    = (const float*)d_in[0];
    const int*   ei   = (const int*)d_in[1];
    const float* Wl1  = (const float*)d_in[2];
    const float* Wr1  = (const float*)d_in[3];
    const float* att1 = (const float*)d_in[4];
    const float* b1   = (const float*)d_in[5];
    const float* Wl2  = (const float*)d_in[6];
    const float* Wr2  = (const float*)d_in[7];
    const float* att2 = (const float*)d_in[8];
    const float* b2   = (const float*)d_in[9];
    float* out = (float*)d_out;

    __half *p_xl1, *p_xr1, *p_h, *p_xl2, *p_xr2;
    cudaGetSymbolAddress((void**)&p_xl1, g_xl1);
    cudaGetSymbolAddress((void**)&p_xr1, g_xr1);
    cudaGetSymbolAddress((void**)&p_h,   g_h);
    cudaGetSymbolAddress((void**)&p_xl2, g_xl2);
    cudaGetSymbolAddress((void**)&p_xr2, g_xr2);

    const int smem = (128 * 136 + 64 * 136) * (int)sizeof(__half);  /* 52224 */
    cudaFuncSetAttribute((const void*)gemm_fp16<128, false, float>,
                         cudaFuncAttributeMaxDynamicSharedMemorySize, smem);
    cudaFuncSetAttribute((const void*)gemm_fp16<64, false, __half>,
                         cudaFuncAttributeMaxDynamicSharedMemorySize, smem);

    const int TB = 256;
    int e8_grid = (EE / 8 + TB) / TB;
    int gemm_grid = (N_NODES + 127) / 128;     /* 391 */

    /* fork: scatter on side stream, gemm1 on main (capturing) stream. */
    cudaStream_t s2;
    cudaStreamCreateWithFlags(&s2, cudaStreamNonBlocking);
    cudaEvent_t evA, evB;
    cudaEventCreateWithFlags(&evA, cudaEventDisableTiming);
    cudaEventCreateWithFlags(&evB, cudaEventDisableTiming);

    cudaEventRecord(evA, 0);
    cudaStreamWaitEvent(s2, evA, 0);
    scatter_kernel<<<e8_grid, TB, 0, s2>>>(ei);
    cudaEventRecord(evB, s2);

    gemm_fp16<128, false, float><<<gemm_grid, TB, smem>>>(x, Wl1, Wr1, nullptr, p_xl1, p_xr1);

    cudaStreamWaitEvent(0, evB, 0);   /* join: node_l1 needs scatter + gemm1 */
    node_l1_kernel<<<(N_NODES * 16 + TB - 1) / TB, TB>>>(att1, b1);

    /* gemm2: h already bias+ELU'd by node_l1 epilogue */
    gemm_fp16<64, false, __half><<<gemm_grid, TB, smem>>>(p_h, Wl2, Wr2, nullptr, p_xl2, p_xr2);
    node_l2_kernel<<<(N_NODES * 8 + TB - 1) / TB, TB>>>(att2, b2, out);
    /* s2/evA/evB intentionally not destroyed (graph-capture safety; no
       tracked device memory held). */
}